// round 10
// baseline (speedup 1.0000x reference)
#include <cuda_runtime.h>
#include <stdint.h>

// MultiEchoNeighborBlock: per-pixel 7x7 KNN (k=9) over point distances,
// gather range values in exact rank order, 20->32 linear + leaky relu.
//
// R10 vs R9 (152.1us, alu=68.8, fma=29.8, issue=73.9): issue/latency attack.
// Evidence: alu dropped 11pts (R9 pipe shift) with only -2.5% time, occupancy
// moves were neutral/negative (R7) -> limiter is the 26% idle issue slots
// caused by serial insert-chain dependencies (2 chains/thread).
// Change: split each echo's candidates into X = rows 0..3 (idx 0..27) and
// Y = rows 4..6 (idx 28..48), processed in LOCKSTEP -> 4 independent chains
// per thread. Then stable truncated merge: Y[s] inserted into slots s..8
// (final rank of Y[s] is >= s), 45 stages/echo. Index-dominant contiguous
// split + strict-< sticky insert => exact top_k stable order (R5 proof).
// Cost +6% instrs for ~+12pt issue. Flavors as R9: echo0 fma-pipe payload
// blends, echo1 alu selects.

#define HH 64
#define WW 2048
#define HWP (HH * WW)
#define NCH 8
#define BX 128        // pixels along W per block
#define BY 2          // rows per block
#define TPB (BX * BY)
#define TW (BX + 6)   // tile width  (halo 3 each side)
#define TH (BY + 6)   // tile height

// alu-flavor sticky stable insert into ascending ak[START..8].
// Ties: incoming (later index) sinks below equal residents; residents never
// re-compared -> exact stable order. 1 FSETP + 4 SEL per stage.
template <int START>
__device__ __forceinline__ void insA(float kin, float vin,
                                     float (&ak)[9], float (&av)[9]) {
    bool p = false;
    float ck = kin, cv = vin;
#pragma unroll
    for (int j = START; j < 9; ++j) {
        p = p | (kin < ak[j]);
        float tk = ak[j], tv = av[j];
        ak[j] = p ? ck : tk;
        av[j] = p ? cv : tv;
        ck = p ? tk : ck;
        cv = p ? tv : cv;
    }
}

// fma-flavor: keys via FMNMX carry identity, payload via FSET mask + FFMA
// blends (m in {0,1}: exact when 0, <=1ulp move when 1 -- payloads feed only
// the linear layer, never an ordering decision).
template <int START>
__device__ __forceinline__ void insF(float kin, float vin,
                                     float (&ak)[9], float (&av)[9]) {
    float ck = kin, cv = vin;
#pragma unroll
    for (int j = START; j < 9; ++j) {
        float aj = ak[j];
        float m;
        asm("set.lt.f32.f32 %0, %1, %2;" : "=f"(m) : "f"(kin), "f"(aj));
        float mn = fminf(ck, aj);
        float mx = fmaxf(ck, aj);
        float diff = __fadd_rn(cv, -av[j]);
        av[j] = __fmaf_rn(m, diff, av[j]);
        cv    = __fmaf_rn(-m, diff, cv);
        ak[j] = mn;
        ck = mx;
    }
}

struct Q6 { float q0x, q0y, q0z, q1x, q1y, q1z; };

// One candidate into one (echo0, echo1) array pair.
__device__ __forceinline__ void do_cand(const float4 p, const Q6& q,
                                        float (&k0)[9], float (&v0)[9],
                                        float (&k1)[9], float (&v1)[9]) {
    // Distances: no FMA contraction (match XLA mul/add rounding), IEEE sqrt
    // (match jnp.sqrt) so the tie pattern is bit-identical to reference.
    float d0x = __fadd_rn(q.q0x, -p.x);
    float d0y = __fadd_rn(q.q0y, -p.y);
    float d0z = __fadd_rn(q.q0z, -p.z);
    float s0 = __fadd_rn(__fadd_rn(__fmul_rn(d0x, d0x), __fmul_rn(d0y, d0y)),
                         __fmul_rn(d0z, d0z));
    insF<0>(__fsqrt_rn(s0), p.w, k0, v0);

    float d1x = __fadd_rn(q.q1x, -p.x);
    float d1y = __fadd_rn(q.q1y, -p.y);
    float d1z = __fadd_rn(q.q1z, -p.z);
    float s1 = __fadd_rn(__fadd_rn(__fmul_rn(d1x, d1x), __fmul_rn(d1y, d1y)),
                         __fmul_rn(d1z, d1z));
    insA<0>(__fsqrt_rn(s1), p.w, k1, v1);
}

__global__ __launch_bounds__(TPB)
void knn_block_kernel(const float* __restrict__ x,
                      const float* __restrict__ rw,
                      float* __restrict__ out) {
    __shared__ float4 tile[TH][TW];   // (px, py, pz, range_ch0)
    __shared__ float wt[20][32];      // transposed weights: wt[c][k]

    const int tid = threadIdx.x;
    const int b = blockIdx.z;
    const int h0 = blockIdx.y * BY;
    const int w0 = blockIdx.x * BX;
    const float* X = x + (size_t)b * NCH * HWP;

    for (int i = tid; i < 640; i += TPB) {
        wt[i % 20][i / 20] = rw[i];
    }
    for (int i = tid; i < TH * TW; i += TPB) {
        int r = i / TW, c = i % TW;
        int gh = h0 - 3 + r, gw = w0 - 3 + c;
        float4 v = make_float4(0.f, 0.f, 0.f, 0.f);
        if (gh >= 0 && gh < HH && gw >= 0 && gw < WW) {
            int o = gh * WW + gw;
            v.x = X[2 * HWP + o];
            v.y = X[3 * HWP + o];
            v.z = X[4 * HWP + o];
            v.w = X[0 * HWP + o];
        }
        tile[r][c] = v;
    }
    __syncthreads();

    const int tx = tid % BX;
    const int ty = tid / BX;
    const int h = h0 + ty;
    const int w = w0 + tx;
    const int pix = h * WW + w;

    const float4 c4 = tile[ty + 3][tx + 3];
    Q6 q;
    q.q0x = c4.x; q.q0y = c4.y; q.q0z = c4.z;
    q.q1x = X[5 * HWP + pix];
    q.q1y = X[6 * HWP + pix];
    q.q1z = X[7 * HWP + pix];
    const float r1c = X[1 * HWP + pix];

    const float INF = __int_as_float(0x7f800000);
    // X-arrays: candidates rows 0..3 (idx 0..27); Y-arrays: rows 4..6 (28..48).
    float xk0[9], xv0[9], xk1[9], xv1[9];
    float yk0[9], yv0[9], yk1[9], yv1[9];
#pragma unroll
    for (int j = 0; j < 9; ++j) {
        xk0[j] = INF; xv0[j] = 0.f; xk1[j] = INF; xv1[j] = 0.f;
        yk0[j] = INF; yv0[j] = 0.f; yk1[j] = INF; yv1[j] = 0.f;
    }

    // Rows 0..2 (X) processed in lockstep with rows 4..6 (Y): 4 live chains.
#pragma unroll 1
    for (int i = 0; i < 3; ++i) {
        const float4* rowX = &tile[ty + i][tx];
        const float4* rowY = &tile[ty + 4 + i][tx];
#pragma unroll
        for (int dx = 0; dx < 7; ++dx) {
            do_cand(rowX[dx], q, xk0, xv0, xk1, xv1);
            do_cand(rowY[dx], q, yk0, yv0, yk1, yv1);
        }
    }
    // Row 3 -> X only.
    {
        const float4* rowX = &tile[ty + 3][tx];
#pragma unroll
        for (int dx = 0; dx < 7; ++dx)
            do_cand(rowX[dx], q, xk0, xv0, xk1, xv1);
    }

    // Stable truncated merge: Y[s] has final rank >= s -> insert into s..8.
    // All Y indices > all X indices, strict < => exact stable order.
    insF<0>(yk0[0], yv0[0], xk0, xv0);
    insF<1>(yk0[1], yv0[1], xk0, xv0);
    insF<2>(yk0[2], yv0[2], xk0, xv0);
    insF<3>(yk0[3], yv0[3], xk0, xv0);
    insF<4>(yk0[4], yv0[4], xk0, xv0);
    insF<5>(yk0[5], yv0[5], xk0, xv0);
    insF<6>(yk0[6], yv0[6], xk0, xv0);
    insF<7>(yk0[7], yv0[7], xk0, xv0);
    insF<8>(yk0[8], yv0[8], xk0, xv0);

    insA<0>(yk1[0], yv1[0], xk1, xv1);
    insA<1>(yk1[1], yv1[1], xk1, xv1);
    insA<2>(yk1[2], yv1[2], xk1, xv1);
    insA<3>(yk1[3], yv1[3], xk1, xv1);
    insA<4>(yk1[4], yv1[4], xk1, xv1);
    insA<5>(yk1[5], yv1[5], xk1, xv1);
    insA<6>(yk1[6], yv1[6], xk1, xv1);
    insA<7>(yk1[7], yv1[7], xk1, xv1);
    insA<8>(yk1[8], yv1[8], xk1, xv1);

    // Features: payloads sorted in rank order.
    float feats[20];
#pragma unroll
    for (int s = 0; s < 9; ++s) {
        feats[s]      = xv0[s];
        feats[10 + s] = xv1[s];
    }
    feats[9]  = c4.w;  // center range ch0
    feats[19] = r1c;   // center range ch1

    // 20 -> 32 linear
    float acc[32];
#pragma unroll
    for (int k = 0; k < 32; ++k) acc[k] = 0.f;
#pragma unroll
    for (int c = 0; c < 20; ++c) {
        float f = feats[c];
        const float4* wp = (const float4*)&wt[c][0];
#pragma unroll
        for (int k4 = 0; k4 < 8; ++k4) {
            float4 wv = wp[k4];
            acc[k4 * 4 + 0] += f * wv.x;
            acc[k4 * 4 + 1] += f * wv.y;
            acc[k4 * 4 + 2] += f * wv.z;
            acc[k4 * 4 + 3] += f * wv.w;
        }
    }

    float* O = out + (size_t)b * 32 * HWP + pix;
#pragma unroll
    for (int k = 0; k < 32; ++k) {
        float v = acc[k];
        v = fmaxf(v, 0.01f * v);   // leaky_relu(0.01)
        O[(size_t)k * HWP] = v;
    }
}

extern "C" void kernel_launch(void* const* d_in, const int* in_sizes, int n_in,
                              void* d_out, int out_size) {
    const float* x  = (const float*)d_in[0];
    const float* rw = (const float*)d_in[1];
    if (n_in >= 2 && in_sizes[0] == 640) {
        const float* t = x; x = rw; rw = t;
    }
    dim3 grid(WW / BX, HH / BY, 4);
    knn_block_kernel<<<grid, TPB>>>(x, rw, (float*)d_out);
}

// round 11
// speedup vs baseline: 1.2182x; 1.2182x over previous
#include <cuda_runtime.h>
#include <stdint.h>

// MultiEchoNeighborBlock: per-pixel 7x7 KNN (k=9) over point distances,
// gather range values in exact rank order, 20->32 linear + leaky relu.
//
// R11 vs R9 (152.1us best; R10's 4-chain ILP regressed to 172us via regs=111,
// occ 23.8 -> ILP must be register-neutral). Two register-neutral changes:
//  1. Triangle inserts: candidate i only needs min(i+1,9) chain stages (slots
//     beyond hold INF; stages there provably no-op). First 9 candidates: 45
//     stages vs 81, per echo -> ~-5% instructions. Bit-identical result.
//  2. insA predicates de-stickified: array is sorted so (kin < ak[j]) is
//     monotone in j; the OR accumulator was redundant serialization. All 9
//     FSETPs now independent -> shorter dependence chains, same predicates.
// Flavors as R9: echo0 = fma-pipe payload blends, echo1 = alu selects.

#define HH 64
#define WW 2048
#define HWP (HH * WW)
#define NCH 8
#define BX 128        // pixels along W per block
#define BY 2          // rows per block
#define TPB (BX * BY)
#define TW (BX + 6)   // tile width  (halo 3 each side)
#define TH (BY + 6)   // tile height

// alu-flavor stable insert, M chain stages (array holds >= M-1 elements).
// Independent predicates: ak sorted ascending => (kin < ak[j]) monotone in j,
// equivalent to the sticky-OR form but with no serial predicate chain.
// Ties: kin == resident -> p false -> incoming (later index) sinks below all
// equal residents; displaced residents shift without re-comparison -> exact
// top_k stable order.
template <int M>
__device__ __forceinline__ void insA(float kin, float vin,
                                     float (&ak)[9], float (&av)[9]) {
    float ck = kin, cv = vin;
#pragma unroll
    for (int j = 0; j < M; ++j) {
        bool pj = kin < ak[j];     // independent per-slot predicate
        float tk = ak[j], tv = av[j];
        ak[j] = pj ? ck : tk;
        av[j] = pj ? cv : tv;
        ck = pj ? tk : ck;
        cv = pj ? tv : cv;
    }
}

// fma-flavor: keys via FMNMX running-carry identity (exact for min/max of
// non-NaN values); payload via FSET float mask + FFMA blends. m in {0,1}:
// exact move when m=0, <=1ulp when m=1 -- payloads feed only the linear
// layer, never an ordering decision. Masks compare the ORIGINAL kin ->
// same stable-tie semantics as insA.
template <int M>
__device__ __forceinline__ void insF(float kin, float vin,
                                     float (&ak)[9], float (&av)[9]) {
    float ck = kin, cv = vin;
#pragma unroll
    for (int j = 0; j < M; ++j) {
        float aj = ak[j];
        float m;
        asm("set.lt.f32.f32 %0, %1, %2;" : "=f"(m) : "f"(kin), "f"(aj));
        float mn = fminf(ck, aj);
        float mx = fmaxf(ck, aj);
        float diff = __fadd_rn(cv, -av[j]);
        av[j] = __fmaf_rn(m, diff, av[j]);
        cv    = __fmaf_rn(-m, diff, cv);
        ak[j] = mn;
        ck = mx;
    }
}

struct Q6 { float q0x, q0y, q0z, q1x, q1y, q1z; };

// One candidate into both echoes' arrays, M chain stages each.
template <int M>
__device__ __forceinline__ void do_cand(const float4 p, const Q6& q,
                                        float (&k0)[9], float (&v0)[9],
                                        float (&k1)[9], float (&v1)[9]) {
    // Distances: no FMA contraction (match XLA mul/add rounding), IEEE sqrt
    // (match jnp.sqrt) so the tie pattern is bit-identical to reference.
    float d0x = __fadd_rn(q.q0x, -p.x);
    float d0y = __fadd_rn(q.q0y, -p.y);
    float d0z = __fadd_rn(q.q0z, -p.z);
    float s0 = __fadd_rn(__fadd_rn(__fmul_rn(d0x, d0x), __fmul_rn(d0y, d0y)),
                         __fmul_rn(d0z, d0z));
    insF<M>(__fsqrt_rn(s0), p.w, k0, v0);

    float d1x = __fadd_rn(q.q1x, -p.x);
    float d1y = __fadd_rn(q.q1y, -p.y);
    float d1z = __fadd_rn(q.q1z, -p.z);
    float s1 = __fadd_rn(__fadd_rn(__fmul_rn(d1x, d1x), __fmul_rn(d1y, d1y)),
                         __fmul_rn(d1z, d1z));
    insA<M>(__fsqrt_rn(s1), p.w, k1, v1);
}

__global__ __launch_bounds__(TPB)
void knn_block_kernel(const float* __restrict__ x,
                      const float* __restrict__ rw,
                      float* __restrict__ out) {
    __shared__ float4 tile[TH][TW];   // (px, py, pz, range_ch0)
    __shared__ float wt[20][32];      // transposed weights: wt[c][k]

    const int tid = threadIdx.x;
    const int b = blockIdx.z;
    const int h0 = blockIdx.y * BY;
    const int w0 = blockIdx.x * BX;
    const float* X = x + (size_t)b * NCH * HWP;

    for (int i = tid; i < 640; i += TPB) {
        wt[i % 20][i / 20] = rw[i];
    }
    for (int i = tid; i < TH * TW; i += TPB) {
        int r = i / TW, c = i % TW;
        int gh = h0 - 3 + r, gw = w0 - 3 + c;
        float4 v = make_float4(0.f, 0.f, 0.f, 0.f);
        if (gh >= 0 && gh < HH && gw >= 0 && gw < WW) {
            int o = gh * WW + gw;
            v.x = X[2 * HWP + o];
            v.y = X[3 * HWP + o];
            v.z = X[4 * HWP + o];
            v.w = X[0 * HWP + o];
        }
        tile[r][c] = v;
    }
    __syncthreads();

    const int tx = tid % BX;
    const int ty = tid / BX;
    const int h = h0 + ty;
    const int w = w0 + tx;
    const int pix = h * WW + w;

    const float4 c4 = tile[ty + 3][tx + 3];
    Q6 q;
    q.q0x = c4.x; q.q0y = c4.y; q.q0z = c4.z;
    q.q1x = X[5 * HWP + pix];
    q.q1y = X[6 * HWP + pix];
    q.q1z = X[7 * HWP + pix];
    const float r1c = X[1 * HWP + pix];

    const float INF = __int_as_float(0x7f800000);
    float ak0[9], av0[9], ak1[9], av1[9];
#pragma unroll
    for (int j = 0; j < 9; ++j) {
        ak0[j] = INF; av0[j] = 0.f;
        ak1[j] = INF; av1[j] = 0.f;
    }

    // Triangle phase: candidate i needs only i+1 chain stages.
    {
        const float4* r0 = &tile[ty + 0][tx];
        do_cand<1>(r0[0], q, ak0, av0, ak1, av1);
        do_cand<2>(r0[1], q, ak0, av0, ak1, av1);
        do_cand<3>(r0[2], q, ak0, av0, ak1, av1);
        do_cand<4>(r0[3], q, ak0, av0, ak1, av1);
        do_cand<5>(r0[4], q, ak0, av0, ak1, av1);
        do_cand<6>(r0[5], q, ak0, av0, ak1, av1);
        do_cand<7>(r0[6], q, ak0, av0, ak1, av1);
        const float4* r1 = &tile[ty + 1][tx];
        do_cand<8>(r1[0], q, ak0, av0, ak1, av1);
        do_cand<9>(r1[1], q, ak0, av0, ak1, av1);
        do_cand<9>(r1[2], q, ak0, av0, ak1, av1);
        do_cand<9>(r1[3], q, ak0, av0, ak1, av1);
        do_cand<9>(r1[4], q, ak0, av0, ak1, av1);
        do_cand<9>(r1[5], q, ak0, av0, ak1, av1);
        do_cand<9>(r1[6], q, ak0, av0, ak1, av1);
    }
    // Steady phase: rows 2..6.
#pragma unroll 1
    for (int dy = 2; dy < 7; ++dy) {
        const float4* row = &tile[ty + dy][tx];
#pragma unroll
        for (int dx = 0; dx < 7; ++dx)
            do_cand<9>(row[dx], q, ak0, av0, ak1, av1);
    }

    // Features: payloads sorted in rank order.
    float feats[20];
#pragma unroll
    for (int s = 0; s < 9; ++s) {
        feats[s]      = av0[s];
        feats[10 + s] = av1[s];
    }
    feats[9]  = c4.w;  // center range ch0
    feats[19] = r1c;   // center range ch1

    // 20 -> 32 linear
    float acc[32];
#pragma unroll
    for (int k = 0; k < 32; ++k) acc[k] = 0.f;
#pragma unroll
    for (int c = 0; c < 20; ++c) {
        float f = feats[c];
        const float4* wp = (const float4*)&wt[c][0];
#pragma unroll
        for (int k4 = 0; k4 < 8; ++k4) {
            float4 wv = wp[k4];
            acc[k4 * 4 + 0] += f * wv.x;
            acc[k4 * 4 + 1] += f * wv.y;
            acc[k4 * 4 + 2] += f * wv.z;
            acc[k4 * 4 + 3] += f * wv.w;
        }
    }

    float* O = out + (size_t)b * 32 * HWP + pix;
#pragma unroll
    for (int k = 0; k < 32; ++k) {
        float v = acc[k];
        v = fmaxf(v, 0.01f * v);   // leaky_relu(0.01)
        O[(size_t)k * HWP] = v;
    }
}

extern "C" void kernel_launch(void* const* d_in, const int* in_sizes, int n_in,
                              void* d_out, int out_size) {
    const float* x  = (const float*)d_in[0];
    const float* rw = (const float*)d_in[1];
    if (n_in >= 2 && in_sizes[0] == 640) {
        const float* t = x; x = rw; rw = t;
    }
    dim3 grid(WW / BX, HH / BY, 4);
    knn_block_kernel<<<grid, TPB>>>(x, rw, (float*)d_out);
}